// round 3
// baseline (speedup 1.0000x reference)
#include <cuda_runtime.h>
#include <cuda_bf16.h>

// ANFIS fuzzy inference, batch=2M rows x 4 features.
// out = sum_j(w_j * clip(conseq_j)) / max(sum_j w_j, 1e-8),
// w_j = prod of 4 Gaussian memberships.
//
// Optimizations:
//  - exp2 prescale: mu_i = ex2(-(d_i')^2), d_i' = x*a' + b', with
//    a' = (1/sigma)*sqrt(0.5*log2(e)) — saves one FMUL per membership.
//  - pair-product CSE: P[9] = mu[0..2]x mu[3..5], Q[6] = mu[6..8]x mu[9..10].
//  - group factorization: rules grouped by shared Q factor:
//    acc = sum_g Q_g * (sum_{j in g} P_{p(j)} * cq_j), wsum analogous.
//  - packed fp32x2: two rows per thread computed with fma/mul/add.rn.f32x2.
//  - constants pre-packed (v,v) in smem, broadcast LDS.64 per use (low regs).

namespace {
// Rules re-sorted by Q-group (q = (ante2-6)*2 + (ante3-9)); verified against
// RULE_ANTECEDENTS. p = ante0*3 + (ante1-3).
__device__ constexpr int GRP_OFF[7] = {0, 7, 11, 16, 21, 26, 30};
__device__ constexpr int GRP_P[30]  = {0,3,1,2,8,5,7,  8,7,5,4,  0,4,3,6,5,
                                       0,1,3,2,8,  0,1,3,2,7,  0,1,3,4};
__device__ constexpr int GRP_CQ[30] = {9,13,15,19,23,27,28,  22,24,25,29,
                                       2,11,17,18,20,  4,10,12,14,26,
                                       0,3,6,7,21,  1,5,8,16};
__device__ constexpr int DM[11] = {0,0,0,1,1,1,2,2,2,3,3};
}

using u64 = unsigned long long;

__device__ __forceinline__ u64 pk2(float lo, float hi) {
    u64 r; asm("mov.b64 %0, {%1, %2};" : "=l"(r) : "f"(lo), "f"(hi)); return r;
}
__device__ __forceinline__ void upk2(u64 v, float& lo, float& hi) {
    asm("mov.b64 {%0, %1}, %2;" : "=f"(lo), "=f"(hi) : "l"(v));
}
__device__ __forceinline__ u64 fma2(u64 a, u64 b, u64 c) {
    u64 d; asm("fma.rn.f32x2 %0, %1, %2, %3;" : "=l"(d) : "l"(a), "l"(b), "l"(c)); return d;
}
__device__ __forceinline__ u64 mul2(u64 a, u64 b) {
    u64 d; asm("mul.rn.f32x2 %0, %1, %2;" : "=l"(d) : "l"(a), "l"(b)); return d;
}
__device__ __forceinline__ u64 add2(u64 a, u64 b) {
    u64 d; asm("add.rn.f32x2 %0, %1, %2;" : "=l"(d) : "l"(a), "l"(b)); return d;
}
// ex2(-t): sign flip via XOR (alu pipe), MUFU.EX2.
__device__ __forceinline__ float ex2neg(float t) {
    float nt = __int_as_float(__float_as_int(t) ^ 0x80000000);
    float r; asm("ex2.approx.ftz.f32 %0, %1;" : "=f"(r) : "f"(nt)); return r;
}

constexpr int THREADS = 256;
constexpr int ROWS_PER_THREAD = 4;   // = 2 packed pairs
constexpr int TILE = THREADS * ROWS_PER_THREAD;

struct SmemConsts {
    u64 a2[11];   // (a', a')
    u64 b2[11];   // (b', b')
    u64 cq2[30];  // (cq, cq)
};

// Packed evaluation of one row pair. xp[4] = packed x per dim.
__device__ __forceinline__ u64 anfis_pair(const u64 xp[4], const SmemConsts& sc)
{
    // 11 memberships, packed
    u64 mu[11];
    #pragma unroll
    for (int i = 0; i < 11; i++) {
        u64 d = fma2(xp[DM[i]], sc.a2[i], sc.b2[i]);
        u64 t = mul2(d, d);
        float tl, th; upk2(t, tl, th);
        mu[i] = pk2(ex2neg(tl), ex2neg(th));
    }

    // Pair products
    u64 Pv[9], Qv[6];
    #pragma unroll
    for (int i = 0; i < 3; i++)
        #pragma unroll
        for (int j = 0; j < 3; j++)
            Pv[i * 3 + j] = mul2(mu[i], mu[3 + j]);
    #pragma unroll
    for (int i = 0; i < 3; i++)
        #pragma unroll
        for (int j = 0; j < 2; j++)
            Qv[i * 2 + j] = mul2(mu[6 + i], mu[9 + j]);

    // Group-factorized rule sums
    u64 acc  = pk2(0.0f, 0.0f);
    u64 wsum = acc;
    #pragma unroll
    for (int g = 0; g < 6; g++) {
        const int m0 = GRP_OFF[g], m1 = GRP_OFF[g + 1];
        u64 s1 = mul2(Pv[GRP_P[m0]], sc.cq2[GRP_CQ[m0]]);
        u64 s0 = Pv[GRP_P[m0]];
        #pragma unroll
        for (int m = m0 + 1; m < m1; m++) {
            s1 = fma2(Pv[GRP_P[m]], sc.cq2[GRP_CQ[m]], s1);
            s0 = add2(s0, Pv[GRP_P[m]]);
        }
        acc  = fma2(Qv[g], s1, acc);
        wsum = fma2(Qv[g], s0, wsum);
    }

    float al, ah, wl, wh;
    upk2(acc, al, ah);
    upk2(wsum, wl, wh);
    float rl = __fdividef(al, fmaxf(wl, 1e-8f));
    float rh = __fdividef(ah, fmaxf(wh, 1e-8f));
    return pk2(rl, rh);
}

// Scalar fallback for the tail.
__device__ __forceinline__ float anfis_row_scalar(float4 xv, const SmemConsts& sc)
{
    const float xd[4] = {xv.x, xv.y, xv.z, xv.w};
    float mu[11];
    #pragma unroll
    for (int i = 0; i < 11; i++) {
        float a = ((const float*)&sc.a2[i])[0];
        float b = ((const float*)&sc.b2[i])[0];
        float d = fmaf(xd[DM[i]], a, b);
        mu[i] = ex2neg(d * d);
    }
    float Pv[9], Qv[6];
    #pragma unroll
    for (int i = 0; i < 3; i++)
        #pragma unroll
        for (int j = 0; j < 3; j++)
            Pv[i * 3 + j] = mu[i] * mu[3 + j];
    #pragma unroll
    for (int i = 0; i < 3; i++)
        #pragma unroll
        for (int j = 0; j < 2; j++)
            Qv[i * 2 + j] = mu[6 + i] * mu[9 + j];

    float acc = 0.0f, wsum = 0.0f;
    #pragma unroll
    for (int g = 0; g < 6; g++) {
        const int m0 = GRP_OFF[g], m1 = GRP_OFF[g + 1];
        float s1 = Pv[GRP_P[m0]] * ((const float*)&sc.cq2[GRP_CQ[m0]])[0];
        float s0 = Pv[GRP_P[m0]];
        #pragma unroll
        for (int m = m0 + 1; m < m1; m++) {
            s1 = fmaf(Pv[GRP_P[m]], ((const float*)&sc.cq2[GRP_CQ[m]])[0], s1);
            s0 += Pv[GRP_P[m]];
        }
        acc  = fmaf(Qv[g], s1, acc);
        wsum = fmaf(Qv[g], s0, wsum);
    }
    return __fdividef(acc, fmaxf(wsum, 1e-8f));
}

__global__ void __launch_bounds__(THREADS, 3)
anfis_kernel(const float4* __restrict__ x,
             const float*  __restrict__ c,
             const float*  __restrict__ log_s,
             const float*  __restrict__ conseq,
             float* __restrict__ out,
             int n)
{
    __shared__ SmemConsts sc;

    const int t = threadIdx.x;
    // Prescale: a' = (1/sigma)*KS, b' = -c*(1/sigma)*KS, KS = sqrt(0.5*log2 e)
    // so mu = ex2(-(x*a'+b')^2) = exp(-0.5*((x-c)/sigma)^2).
    if (t < 11) {
        const float KS = 0.8493218002880191f;  // sqrt(0.5 * log2(e))
        float ci  = __ldg(c + t);
        float sg  = fmaxf(__expf(__ldg(log_s + t)), 0.001f);
        float ap  = KS / sg;
        sc.a2[t] = pk2(ap, ap);
        float bp  = -ci * ap;
        sc.b2[t] = pk2(bp, bp);
    }
    if (t < 30) {
        float v = fminf(fmaxf(__ldg(conseq + t), 0.0f), 100.0f);
        sc.cq2[t] = pk2(v, v);
    }
    __syncthreads();

    const int base = blockIdx.x * TILE + t;

    if (blockIdx.x * TILE + TILE <= n) {
        // Full tile: 4 coalesced LDG.128, rows paired (k, k+1)->(base+k*T, base+(k+1)*T).
        float4 xv[ROWS_PER_THREAD];
        #pragma unroll
        for (int k = 0; k < ROWS_PER_THREAD; k++)
            xv[k] = __ldg(x + base + k * THREADS);

        #pragma unroll
        for (int p = 0; p < ROWS_PER_THREAD / 2; p++) {
            const float4 lo = xv[2 * p], hi = xv[2 * p + 1];
            u64 xp[4] = { pk2(lo.x, hi.x), pk2(lo.y, hi.y),
                          pk2(lo.z, hi.z), pk2(lo.w, hi.w) };
            u64 res = anfis_pair(xp, sc);
            float rl, rh; upk2(res, rl, rh);
            out[base + (2 * p)     * THREADS] = rl;
            out[base + (2 * p + 1) * THREADS] = rh;
        }
    } else {
        // Tail: predicated scalar path.
        #pragma unroll
        for (int k = 0; k < ROWS_PER_THREAD; k++) {
            int r = base + k * THREADS;
            if (r < n) {
                float4 xv = __ldg(x + r);
                out[r] = anfis_row_scalar(xv, sc);
            }
        }
    }
}

extern "C" void kernel_launch(void* const* d_in, const int* in_sizes, int n_in,
                              void* d_out, int out_size)
{
    const float* x      = (const float*)d_in[0];
    const float* c      = (const float*)d_in[1];
    const float* log_s  = (const float*)d_in[2];
    const float* conseq = (const float*)d_in[3];
    float* out          = (float*)d_out;

    int n = in_sizes[0] / 4;   // rows
    int blocks = (n + TILE - 1) / TILE;

    anfis_kernel<<<blocks, THREADS>>>((const float4*)x, c, log_s, conseq, out, n);
}

// round 4
// speedup vs baseline: 2.0470x; 2.0470x over previous
#include <cuda_runtime.h>
#include <cuda_bf16.h>

// ANFIS fuzzy inference, batch=2M rows x 4 features.
// out = sum_j(w_j * clip(conseq_j)) / max(sum_j w_j, 1e-8),
// w_j = prod of 4 Gaussian memberships.
//
// Scalar math, constants in registers (R2 structure), plus:
//  - exp2 prescale: mu_i = ex2(-(x*a'+b')^2), a' = (1/sigma)*sqrt(0.5*log2 e)
//    (sign flip via XOR on the alu pipe; MUFU.EX2 direct).
//  - pair-product CSE: P[9] = mu[0..2] x mu[3..5], Q[6] = mu[6..8] x mu[9..10].
//  - group factorization over shared Q factors:
//    acc = sum_g Q_g * (sum_{j in g} P_{p(j)} * cq_j); wsum analogous.

namespace {
// Rules grouped by q = (ante2-6)*2 + (ante3-9); p = ante0*3 + (ante1-3).
// Verified against RULE_ANTECEDENTS.
__device__ constexpr int GRP_OFF[7] = {0, 7, 11, 16, 21, 26, 30};
__device__ constexpr int GRP_P[30]  = {0,3,1,2,8,5,7,  8,7,5,4,  0,4,3,6,5,
                                       0,1,3,2,8,  0,1,3,2,7,  0,1,3,4};
__device__ constexpr int GRP_CQ[30] = {9,13,15,19,23,27,28,  22,24,25,29,
                                       2,11,17,18,20,  4,10,12,14,26,
                                       0,3,6,7,21,  1,5,8,16};
__device__ constexpr int DM[11] = {0,0,0,1,1,1,2,2,2,3,3};
}

// ex2(-t): sign flip (alu pipe) + MUFU.EX2.
__device__ __forceinline__ float ex2neg(float t) {
    float nt = __int_as_float(__float_as_int(t) ^ 0x80000000);
    float r; asm("ex2.approx.ftz.f32 %0, %1;" : "=f"(r) : "f"(nt)); return r;
}

constexpr int THREADS = 256;
constexpr int ROWS_PER_THREAD = 4;
constexpr int TILE = THREADS * ROWS_PER_THREAD;   // 1024 rows/block

__device__ __forceinline__ float anfis_row(const float4 xv,
                                           const float* __restrict__ a,
                                           const float* __restrict__ b,
                                           const float* __restrict__ cq)
{
    const float xd[4] = {xv.x, xv.y, xv.z, xv.w};

    // 11 memberships: FFMA + FMUL + XOR + MUFU each.
    float mu[11];
    #pragma unroll
    for (int i = 0; i < 11; i++) {
        float d = fmaf(xd[DM[i]], a[i], b[i]);
        mu[i] = ex2neg(d * d);
    }

    // Pair products.
    float Pv[9], Qv[6];
    #pragma unroll
    for (int i = 0; i < 3; i++)
        #pragma unroll
        for (int j = 0; j < 3; j++)
            Pv[i * 3 + j] = mu[i] * mu[3 + j];
    #pragma unroll
    for (int i = 0; i < 3; i++)
        #pragma unroll
        for (int j = 0; j < 2; j++)
            Qv[i * 2 + j] = mu[6 + i] * mu[9 + j];

    // Group-factorized rule sums: 6 x (1 MUL + (len-1) FMA + (len-1) ADD)
    // + 12 final FMA.
    float acc = 0.0f, wsum = 0.0f;
    #pragma unroll
    for (int g = 0; g < 6; g++) {
        const int m0 = GRP_OFF[g], m1 = GRP_OFF[g + 1];
        float s1 = Pv[GRP_P[m0]] * cq[GRP_CQ[m0]];
        float s0 = Pv[GRP_P[m0]];
        #pragma unroll
        for (int m = m0 + 1; m < m1; m++) {
            s1 = fmaf(Pv[GRP_P[m]], cq[GRP_CQ[m]], s1);
            s0 += Pv[GRP_P[m]];
        }
        acc  = fmaf(Qv[g], s1, acc);
        wsum = fmaf(Qv[g], s0, wsum);
    }

    return __fdividef(acc, fmaxf(wsum, 1e-8f));
}

__global__ void __launch_bounds__(THREADS)
anfis_kernel(const float4* __restrict__ x,
             const float*  __restrict__ c,
             const float*  __restrict__ log_s,
             const float*  __restrict__ conseq,
             float* __restrict__ out,
             int n)
{
    // Per-block constants staged via smem, then held in registers.
    __shared__ float s_a[11], s_b[11], s_cq[30];

    const int t = threadIdx.x;
    if (t < 11) {
        const float KS = 0.8493218002880191f;  // sqrt(0.5 * log2(e))
        float ci  = __ldg(c + t);
        float sg  = fmaxf(__expf(__ldg(log_s + t)), 0.001f);
        float ap  = KS / sg;
        s_a[t] = ap;
        s_b[t] = -ci * ap;
    }
    if (t < 30) {
        s_cq[t] = fminf(fmaxf(__ldg(conseq + t), 0.0f), 100.0f);
    }
    __syncthreads();

    float a[11], b[11], cq[30];
    #pragma unroll
    for (int i = 0; i < 11; i++) { a[i] = s_a[i]; b[i] = s_b[i]; }
    #pragma unroll
    for (int j = 0; j < 30; j++) { cq[j] = s_cq[j]; }

    const int base = blockIdx.x * TILE + t;

    if (blockIdx.x * TILE + TILE <= n) {
        // Full tile: 4 unconditional coalesced LDG.128 (MLP=4).
        float4 xv[ROWS_PER_THREAD];
        #pragma unroll
        for (int k = 0; k < ROWS_PER_THREAD; k++)
            xv[k] = __ldg(x + base + k * THREADS);

        float res[ROWS_PER_THREAD];
        #pragma unroll
        for (int k = 0; k < ROWS_PER_THREAD; k++)
            res[k] = anfis_row(xv[k], a, b, cq);

        #pragma unroll
        for (int k = 0; k < ROWS_PER_THREAD; k++)
            out[base + k * THREADS] = res[k];
    } else {
        // Tail: predicated.
        #pragma unroll
        for (int k = 0; k < ROWS_PER_THREAD; k++) {
            int r = base + k * THREADS;
            if (r < n) {
                float4 xv = __ldg(x + r);
                out[r] = anfis_row(xv, a, b, cq);
            }
        }
    }
}

extern "C" void kernel_launch(void* const* d_in, const int* in_sizes, int n_in,
                              void* d_out, int out_size)
{
    const float* x      = (const float*)d_in[0];
    const float* c      = (const float*)d_in[1];
    const float* log_s  = (const float*)d_in[2];
    const float* conseq = (const float*)d_in[3];
    float* out          = (float*)d_out;

    int n = in_sizes[0] / 4;   // rows
    int blocks = (n + TILE - 1) / TILE;

    anfis_kernel<<<blocks, THREADS>>>((const float4*)x, c, log_s, conseq, out, n);
}